// round 1
// baseline (speedup 1.0000x reference)
#include <cuda_runtime.h>

#define B_   256
#define IN_  256
#define OUT_ 512
#define EPS_ 1e-7f

// Scratch (no allocations allowed in kernel_launch)
__device__ float g_R[B_ * IN_];      // 1/(x[b,i]+eps), layout [b][i]
__device__ float g_colsum[IN_];      // sum_b x[b,i]
__device__ float g_relx[IN_ * OUT_]; // rel_x[i][o]

// ---------------------------------------------------------------------------
// Kernel 0a: R[b,i] = 1/(x[b,i]+eps)
// ---------------------------------------------------------------------------
__global__ void k_prep(const float* __restrict__ x) {
    int idx = blockIdx.x * blockDim.x + threadIdx.x;
    if (idx < B_ * IN_) g_R[idx] = 1.0f / (x[idx] + EPS_);
}

// ---------------------------------------------------------------------------
// Kernel 0b: colsum[i] = sum_b x[b,i]   (one block, 256 threads, coalesced)
// ---------------------------------------------------------------------------
__global__ void k_colsum(const float* __restrict__ x) {
    int i = threadIdx.x;
    float s = 0.0f;
    #pragma unroll 8
    for (int b = 0; b < B_; b++) s += x[b * IN_ + i];
    g_colsum[i] = s;
}

// ---------------------------------------------------------------------------
// Kernel 1: rel_x[i,o] = (sum_b min(t[b,o]*R[b,i], 1)) / colsum[i]
// Tiled 32(i) x 32(o) per block, 256 threads, 2x2 per thread, k-loop over b.
// Grid: (IN/32, OUT/32) = (8, 16) = 128 blocks.
// ---------------------------------------------------------------------------
__global__ void k_relx(const float* __restrict__ t) {
    __shared__ float Rs[32][33];  // [b_local][i_local]
    __shared__ float Ts[32][33];  // [b_local][o_local]

    const int i0 = blockIdx.x * 32;
    const int o0 = blockIdx.y * 32;
    const int lid = threadIdx.x;
    const int tx = lid & 15;   // i direction
    const int ty = lid >> 4;   // o direction

    float acc00 = 0.f, acc01 = 0.f, acc10 = 0.f, acc11 = 0.f;

    for (int bb = 0; bb < B_; bb += 32) {
        #pragma unroll
        for (int k = 0; k < 4; k++) {
            int e  = lid + k * 256;
            int bl = e >> 5;
            int il = e & 31;
            Rs[bl][il] = g_R[(bb + bl) * IN_ + i0 + il];
            Ts[bl][il] = t  [(bb + bl) * OUT_ + o0 + il];
        }
        __syncthreads();

        #pragma unroll
        for (int b = 0; b < 32; b++) {
            float r0 = Rs[b][tx];
            float r1 = Rs[b][tx + 16];
            float t0 = Ts[b][ty];
            float t1 = Ts[b][ty + 16];
            acc00 += fminf(t0 * r0, 1.0f);
            acc01 += fminf(t1 * r0, 1.0f);
            acc10 += fminf(t0 * r1, 1.0f);
            acc11 += fminf(t1 * r1, 1.0f);
        }
        __syncthreads();
    }

    float cs0 = g_colsum[i0 + tx];
    float cs1 = g_colsum[i0 + tx + 16];
    g_relx[(i0 + tx)      * OUT_ + o0 + ty]      = acc00 / cs0;
    g_relx[(i0 + tx)      * OUT_ + o0 + ty + 16] = acc01 / cs0;
    g_relx[(i0 + tx + 16) * OUT_ + o0 + ty]      = acc10 / cs1;
    g_relx[(i0 + tx + 16) * OUT_ + o0 + ty + 16] = acc11 / cs1;
}

// ---------------------------------------------------------------------------
// Kernel 2: ind_x[b,o] = argmax_i x[b,i]*rel_x[i,o] (first-max tie-break);
//           chosen_x[b,o] = x[b,ind]*w[ind,o]
// Tiled 32(b) x 32(o), 256 threads, 2x2 per thread, k-loop over i.
// Grid: (B/32, OUT/32) = (8, 16) = 128 blocks.
// ---------------------------------------------------------------------------
__global__ void k_argmax(const float* __restrict__ x,
                         const float* __restrict__ w,
                         float* __restrict__ outx) {
    __shared__ float Xs[32][33];  // [i_local][b_local]  (transposed x tile)
    __shared__ float Rl[32][33];  // [i_local][o_local]

    const int b0 = blockIdx.x * 32;
    const int o0 = blockIdx.y * 32;
    const int lid = threadIdx.x;
    const int tb = lid & 15;   // b direction
    const int to = lid >> 4;   // o direction

    float best00 = -1.f, best01 = -1.f, best10 = -1.f, best11 = -1.f;
    int   id00 = 0, id01 = 0, id10 = 0, id11 = 0;

    for (int ii = 0; ii < IN_; ii += 32) {
        #pragma unroll
        for (int k = 0; k < 4; k++) {
            int e  = lid + k * 256;
            int r  = e >> 5;
            int c  = e & 31;
            // Xs transposed: Xs[i][b] = x[b0+r][ii+c] -> store Xs[c][r]
            Xs[c][r] = x[(b0 + r) * IN_ + ii + c];
            Rl[r][c] = g_relx[(ii + r) * OUT_ + o0 + c];
        }
        __syncthreads();

        #pragma unroll
        for (int i = 0; i < 32; i++) {
            const int gi = ii + i;
            float x0 = Xs[i][tb];
            float x1 = Xs[i][tb + 16];
            float r0 = Rl[i][to];
            float r1 = Rl[i][to + 16];
            float v;
            v = x0 * r0; if (v > best00) { best00 = v; id00 = gi; }
            v = x0 * r1; if (v > best01) { best01 = v; id01 = gi; }
            v = x1 * r0; if (v > best10) { best10 = v; id10 = gi; }
            v = x1 * r1; if (v > best11) { best11 = v; id11 = gi; }
        }
        __syncthreads();
    }

    const int b_0 = b0 + tb, b_1 = b0 + tb + 16;
    const int o_0 = o0 + to, o_1 = o0 + to + 16;
    outx[b_0 * OUT_ + o_0] = x[b_0 * IN_ + id00] * w[id00 * OUT_ + o_0];
    outx[b_0 * OUT_ + o_1] = x[b_0 * IN_ + id01] * w[id01 * OUT_ + o_1];
    outx[b_1 * OUT_ + o_0] = x[b_1 * IN_ + id10] * w[id10 * OUT_ + o_0];
    outx[b_1 * OUT_ + o_1] = x[b_1 * IN_ + id11] * w[id11 * OUT_ + o_1];
}

// ---------------------------------------------------------------------------
// Kernel 3: iw[o] = argmax_i w[i,o]; chosen_w[b,o] = x[b,iw]*w[iw,o]
// (rel_w is a positive per-(b,o) scalar over IN -> argmax unchanged.)
// Grid: 16 blocks x 256 threads; each block owns 32 consecutive o.
// ---------------------------------------------------------------------------
__global__ void k_chosenw(const float* __restrict__ x,
                          const float* __restrict__ w,
                          float* __restrict__ outw) {
    __shared__ int   s_iw[32];
    __shared__ float s_wv[32];

    const int o0   = blockIdx.x * 32;
    const int warp = threadIdx.x >> 5;
    const int lane = threadIdx.x & 31;

    // Phase 1: each warp does argmax over i for 4 o's
    #pragma unroll
    for (int k = 0; k < 4; k++) {
        int o = o0 + warp * 4 + k;
        float best = -1.f;
        int bi = 0;
        for (int i = lane; i < IN_; i += 32) {
            float v = w[i * OUT_ + o];
            if (v > best) { best = v; bi = i; }
        }
        // warp-reduce argmax, first-index tie-break
        #pragma unroll
        for (int off = 16; off > 0; off >>= 1) {
            float ov = __shfl_down_sync(0xffffffffu, best, off);
            int   oi = __shfl_down_sync(0xffffffffu, bi,   off);
            if (ov > best || (ov == best && oi < bi)) { best = ov; bi = oi; }
        }
        if (lane == 0) { s_iw[warp * 4 + k] = bi; s_wv[warp * 4 + k] = best; }
    }
    __syncthreads();

    // Phase 2: write chosen_w for all b, coalesced over o
    const int ol   = threadIdx.x & 31;
    const int brow = threadIdx.x >> 5;
    const int iw   = s_iw[ol];
    const float wv = s_wv[ol];
    for (int b = brow; b < B_; b += 8) {
        outw[b * OUT_ + o0 + ol] = x[b * IN_ + iw] * wv;
    }
}

// ---------------------------------------------------------------------------
extern "C" void kernel_launch(void* const* d_in, const int* in_sizes, int n_in,
                              void* d_out, int out_size) {
    const float* x = (const float*)d_in[0];
    const float* w = (const float*)d_in[1];
    const float* t = (const float*)d_in[2];
    float* outx = (float*)d_out;                 // chosen_x: [B, OUT]
    float* outw = (float*)d_out + B_ * OUT_;     // chosen_w: [B, OUT]

    k_prep<<<(B_ * IN_ + 255) / 256, 256>>>(x);
    k_colsum<<<1, IN_>>>(x);
    k_relx<<<dim3(IN_ / 32, OUT_ / 32), 256>>>(t);
    k_argmax<<<dim3(B_ / 32, OUT_ / 32), 256>>>(x, w, outx);
    k_chosenw<<<OUT_ / 32, 256>>>(x, w, outw);
}

// round 2
// speedup vs baseline: 1.3892x; 1.3892x over previous
#include <cuda_runtime.h>

#define B_   256
#define IN_  256
#define OUT_ 512
#define EPS_ 1e-7f

// Scratch (no allocations allowed)
__device__ float g_R[B_ * IN_];                 // 1/(x[b,i]+eps)
__device__ float g_colsum[IN_];                 // sum_b x[b,i] (sequential order)
__device__ float g_relx[IN_ * OUT_];            // rel_x[i][o]
__device__ unsigned long long g_key[2 * B_ * OUT_]; // packed argmax partials
__device__ int   g_iw[OUT_];                    // argmax_i w[i,o]
__device__ float g_wv[OUT_];                    // w[iw,o]

// ---------------------------------------------------------------------------
// Kernel A (fused prep): blocks 0..255 -> R rows; block 256 -> colsum;
// blocks 257..272 -> w-column argmax (32 o's each).
// ---------------------------------------------------------------------------
__global__ void kPrep(const float* __restrict__ x, const float* __restrict__ w) {
    const int bid = blockIdx.x;
    const int tid = threadIdx.x;

    if (bid < 256) {
        // one row of R
        int idx = bid * IN_ + tid;
        g_R[idx] = 1.0f / (x[idx] + EPS_);
        return;
    }
    if (bid == 256) {
        // colsum: strictly sequential over b (bit-exact vs R1)
        int i = tid;
        float s = 0.0f;
        #pragma unroll 16
        for (int b = 0; b < B_; b++) s += x[b * IN_ + i];
        g_colsum[i] = s;
        return;
    }
    // w argmax: block handles 32 o's, one warp per 4 o's
    const int o0   = (bid - 257) * 32;
    const int warp = tid >> 5;
    const int lane = tid & 31;
    #pragma unroll
    for (int k = 0; k < 4; k++) {
        int o = o0 + warp * 4 + k;
        float best = -1.f;
        int bi = 0;
        for (int i = lane; i < IN_; i += 32) {
            float v = w[i * OUT_ + o];
            if (v > best) { best = v; bi = i; }
        }
        #pragma unroll
        for (int off = 16; off > 0; off >>= 1) {
            float ov = __shfl_down_sync(0xffffffffu, best, off);
            int   oi = __shfl_down_sync(0xffffffffu, bi,   off);
            if (ov > best || (ov == best && oi < bi)) { best = ov; bi = oi; }
        }
        if (lane == 0) { g_iw[o] = bi; g_wv[o] = best; }
    }
}

// ---------------------------------------------------------------------------
// Kernel B: rel_x[i,o] = (sum_b min(t[b,o]*R[b,i],1)) / colsum[i]
// Tile 32i x 32o, 256 threads, 2x2 per thread via float2, b in 2 chunks of 128
// resident in smem. Grid (8,16)=128 blocks. Sum order: strictly ascending b.
// ---------------------------------------------------------------------------
__global__ void k_relx(const float* __restrict__ t) {
    __shared__ float Rs[128][32];
    __shared__ float Ts[128][32];

    const int i0  = blockIdx.x * 32;
    const int o0  = blockIdx.y * 32;
    const int lid = threadIdx.x;
    const int tx  = lid & 15;   // i pair: 2tx, 2tx+1
    const int ty  = lid >> 4;   // o pair: 2ty, 2ty+1

    float acc00 = 0.f, acc01 = 0.f, acc10 = 0.f, acc11 = 0.f;

    for (int bb = 0; bb < B_; bb += 128) {
        #pragma unroll
        for (int k = 0; k < 4; k++) {
            int e   = lid + k * 256;      // 0..1023
            int row = e >> 3;             // 0..127
            int c4  = (e & 7) * 4;        // 0..28
            *(float4*)&Rs[row][c4] = *(const float4*)&g_R[(bb + row) * IN_  + i0 + c4];
            *(float4*)&Ts[row][c4] = *(const float4*)&t  [(bb + row) * OUT_ + o0 + c4];
        }
        __syncthreads();

        #pragma unroll 8
        for (int b = 0; b < 128; b++) {
            float2 r  = *(const float2*)&Rs[b][2 * tx];
            float2 tt = *(const float2*)&Ts[b][2 * ty];
            acc00 += fminf(tt.x * r.x, 1.0f);
            acc01 += fminf(tt.y * r.x, 1.0f);
            acc10 += fminf(tt.x * r.y, 1.0f);
            acc11 += fminf(tt.y * r.y, 1.0f);
        }
        __syncthreads();
    }

    const int i_0 = i0 + 2 * tx, i_1 = i_0 + 1;
    const int o_0 = o0 + 2 * ty, o_1 = o_0 + 1;
    float cs0 = g_colsum[i_0];
    float cs1 = g_colsum[i_1];
    g_relx[i_0 * OUT_ + o_0] = acc00 / cs0;
    g_relx[i_0 * OUT_ + o_1] = acc01 / cs0;
    g_relx[i_1 * OUT_ + o_0] = acc10 / cs1;
    g_relx[i_1 * OUT_ + o_1] = acc11 / cs1;
}

// ---------------------------------------------------------------------------
// Kernel C: partial argmax over i-halves. Grid (8,16,2)=256 blocks, 256 thr.
// Tile 32b x 32o, each thread 2x2 via float2. i-range = 128 per block.
// Writes packed key = (bits(best)<<32) | ~idx  (max over keys == first-max).
// ---------------------------------------------------------------------------
__global__ void k_argmax(const float* __restrict__ x) {
    __shared__ float Xs[128][34];   // [i][b], pad 34 keeps float2 alignment
    __shared__ float Rl[128][32];   // [i][o]

    const int b0  = blockIdx.x * 32;
    const int o0  = blockIdx.y * 32;
    const int iz  = blockIdx.z * 128;
    const int lid = threadIdx.x;
    const int tb  = lid & 15;   // b pair: 2tb, 2tb+1
    const int to  = lid >> 4;   // o pair: 2to, 2to+1

    // Load x tile transposed: Xs[i][b]
    #pragma unroll
    for (int k = 0; k < 4; k++) {
        int e   = lid + k * 256;          // 0..1023
        int row = e >> 5;                 // b-local 0..31
        int c4  = (e & 31) * 4;           // i-local 0..124
        float4 v = *(const float4*)&x[(b0 + row) * IN_ + iz + c4];
        Xs[c4 + 0][row] = v.x;
        Xs[c4 + 1][row] = v.y;
        Xs[c4 + 2][row] = v.z;
        Xs[c4 + 3][row] = v.w;
    }
    // Load relx tile: Rl[i][o]
    #pragma unroll
    for (int k = 0; k < 4; k++) {
        int e   = lid + k * 256;
        int row = e >> 3;                 // i-local 0..127
        int c4  = (e & 7) * 4;            // o-local
        *(float4*)&Rl[row][c4] = *(const float4*)&g_relx[(iz + row) * OUT_ + o0 + c4];
    }
    __syncthreads();

    float best00 = -1.f, best01 = -1.f, best10 = -1.f, best11 = -1.f;
    int   id00 = 0, id01 = 0, id10 = 0, id11 = 0;

    #pragma unroll 4
    for (int i = 0; i < 128; i++) {
        const int gi = iz + i;
        float2 xv = *(const float2*)&Xs[i][2 * tb];
        float2 rv = *(const float2*)&Rl[i][2 * to];
        float v;
        v = xv.x * rv.x; { bool p = v > best00; best00 = fmaxf(best00, v); if (p) id00 = gi; }
        v = xv.x * rv.y; { bool p = v > best01; best01 = fmaxf(best01, v); if (p) id01 = gi; }
        v = xv.y * rv.x; { bool p = v > best10; best10 = fmaxf(best10, v); if (p) id10 = gi; }
        v = xv.y * rv.y; { bool p = v > best11; best11 = fmaxf(best11, v); if (p) id11 = gi; }
    }

    const int b_0 = b0 + 2 * tb, b_1 = b_0 + 1;
    const int o_0 = o0 + 2 * to, o_1 = o_0 + 1;
    const unsigned long long base = (unsigned long long)blockIdx.z * (B_ * OUT_);
    g_key[base + b_0 * OUT_ + o_0] = ((unsigned long long)__float_as_uint(best00) << 32) | (unsigned int)(~id00);
    g_key[base + b_0 * OUT_ + o_1] = ((unsigned long long)__float_as_uint(best01) << 32) | (unsigned int)(~id01);
    g_key[base + b_1 * OUT_ + o_0] = ((unsigned long long)__float_as_uint(best10) << 32) | (unsigned int)(~id10);
    g_key[base + b_1 * OUT_ + o_1] = ((unsigned long long)__float_as_uint(best11) << 32) | (unsigned int)(~id11);
}

// ---------------------------------------------------------------------------
// Kernel D: combine argmax halves + gather outx; also write outw.
// 128 blocks x 256 threads x 4 outputs, fully coalesced on o.
// ---------------------------------------------------------------------------
__global__ void kOut(const float* __restrict__ x,
                     const float* __restrict__ w,
                     float* __restrict__ outx,
                     float* __restrict__ outw) {
    int g = blockIdx.x * blockDim.x + threadIdx.x;   // 0..32767
    #pragma unroll
    for (int k = 0; k < 4; k++) {
        int e = g + k * 32768;                       // 0..131071
        int b = e >> 9;
        int o = e & 511;
        unsigned long long k0 = g_key[e];
        unsigned long long k1 = g_key[e + B_ * OUT_];
        unsigned long long kk = (k0 >= k1) ? k0 : k1; // tie -> lower half (bigger ~i)
        int i = (int)(~(unsigned int)kk);
        outx[e] = x[b * IN_ + i] * w[i * OUT_ + o];
        outw[e] = x[b * IN_ + g_iw[o]] * g_wv[o];
    }
}

// ---------------------------------------------------------------------------
extern "C" void kernel_launch(void* const* d_in, const int* in_sizes, int n_in,
                              void* d_out, int out_size) {
    const float* x = (const float*)d_in[0];
    const float* w = (const float*)d_in[1];
    const float* t = (const float*)d_in[2];
    float* outx = (float*)d_out;
    float* outw = (float*)d_out + B_ * OUT_;

    kPrep<<<273, 256>>>(x, w);
    k_relx<<<dim3(IN_ / 32, OUT_ / 32), 256>>>(t);
    k_argmax<<<dim3(B_ / 32, OUT_ / 32, 2), 256>>>(x);
    kOut<<<128, 256>>>(x, w, outx, outw);
}